// round 2
// baseline (speedup 1.0000x reference)
#include <cuda_runtime.h>

// Problem constants (fixed by the reference)
#define N_G 8      // latent groups
#define M_C 512    // codebook size
#define D_C 64     // code dim
#define B_S 32     // batch
#define L_S 1024   // seq len
#define BL  (B_S * L_S)       // 32768 tokens per group
#define TOK_PER_CTA 128
#define CHUNK 128             // codes staged in smem per pass (4 passes)

// Scratch (no cudaMalloc allowed)
__device__ int    g_hist[N_G * M_C];
__device__ double g_loss;

__global__ void vq_zero() {
    int i = blockIdx.x * blockDim.x + threadIdx.x;
    if (i < N_G * M_C) g_hist[i] = 0;
    if (i == 0) g_loss = 0.0;
}

// One thread = one token (b,l) of group n.
// Bit-exact emulation of the reference (XLA CPU hypothesis):
//   x2  = sequential scalar:  s = fadd(s, fmul(x_d, x_d)),  d = 0..63
//   e2  = sequential scalar:  s = fadd(s, fmul(e_d, e_d)),  d = 0..63
//   xe  = sequential FMA chain (Eigen gebp): a = fma(x_d, e_d, a), d = 0..63
//   d2  = fadd( fsub( x2, fmul(2, xe) ), e2 )
//   argmin with first-index tie break (strict <)
__global__ __launch_bounds__(TOK_PER_CTA)
void vq_main(const float* __restrict__ x, const float* __restrict__ emb,
             float* __restrict__ out)
{
    const int n = blockIdx.y;
    const int t = blockIdx.x * TOK_PER_CTA + threadIdx.x;  // token id in [0, BL)
    const int b = t >> 10;          // t / L_S
    const int l = t & (L_S - 1);    // t % L_S

    // x[b, n*64+d, l]: stride 1024 over d, lane-contiguous over l (coalesced)
    const float* xbase = x + (size_t)(b * 512 + n * 64) * L_S + l;
    float xr[D_C];
#pragma unroll
    for (int d = 0; d < D_C; d++) xr[d] = xbase[(size_t)d * L_S];

    // x2: strict sequential order, separate mul and add roundings
    float x2 = 0.f;
#pragma unroll
    for (int d = 0; d < D_C; d++) x2 = __fadd_rn(x2, __fmul_rn(xr[d], xr[d]));

    __shared__ float4 esm[CHUNK * (D_C / 4)];   // 128 codes x 64 floats = 32 KB
    __shared__ float  e2s[CHUNK];               // ||e||^2 per staged code (exact order)

    float best  = 3.402823466e38f;
    int   bestm = 0;

    for (int c = 0; c < M_C / CHUNK; c++) {
        __syncthreads();  // protect previous chunk's readers
        const float4* src = (const float4*)(emb + ((size_t)n * M_C + c * CHUNK) * D_C);
        for (int i = threadIdx.x; i < CHUNK * (D_C / 4); i += TOK_PER_CTA)
            esm[i] = src[i];
        __syncthreads();

        // e2 for this chunk: one code per thread, strict sequential order
        {
            const int m = threadIdx.x;   // TOK_PER_CTA == CHUNK
            const float* ep = (const float*)&esm[m * (D_C / 4)];
            float s = 0.f;
#pragma unroll
            for (int d = 0; d < D_C; d++) s = __fadd_rn(s, __fmul_rn(ep[d], ep[d]));
            e2s[m] = s;
        }
        __syncthreads();

        // 8 codes at a time: 8 independent sequential FMA chains (ILP across codes,
        // strict d-order within each chain). All lanes read the same esm word
        // -> smem broadcast, conflict-free.
#pragma unroll 1
        for (int mo = 0; mo < CHUNK; mo += 8) {
            float a0 = 0.f, a1 = 0.f, a2 = 0.f, a3 = 0.f;
            float a4 = 0.f, a5 = 0.f, a6 = 0.f, a7 = 0.f;
#pragma unroll 4
            for (int v = 0; v < D_C / 4; v++) {
                const float xv0 = xr[4 * v + 0], xv1 = xr[4 * v + 1];
                const float xv2 = xr[4 * v + 2], xv3 = xr[4 * v + 3];
                float4 e;
                e = esm[(mo + 0) * 16 + v];
                a0 = __fmaf_rn(xv0, e.x, a0); a0 = __fmaf_rn(xv1, e.y, a0);
                a0 = __fmaf_rn(xv2, e.z, a0); a0 = __fmaf_rn(xv3, e.w, a0);
                e = esm[(mo + 1) * 16 + v];
                a1 = __fmaf_rn(xv0, e.x, a1); a1 = __fmaf_rn(xv1, e.y, a1);
                a1 = __fmaf_rn(xv2, e.z, a1); a1 = __fmaf_rn(xv3, e.w, a1);
                e = esm[(mo + 2) * 16 + v];
                a2 = __fmaf_rn(xv0, e.x, a2); a2 = __fmaf_rn(xv1, e.y, a2);
                a2 = __fmaf_rn(xv2, e.z, a2); a2 = __fmaf_rn(xv3, e.w, a2);
                e = esm[(mo + 3) * 16 + v];
                a3 = __fmaf_rn(xv0, e.x, a3); a3 = __fmaf_rn(xv1, e.y, a3);
                a3 = __fmaf_rn(xv2, e.z, a3); a3 = __fmaf_rn(xv3, e.w, a3);
                e = esm[(mo + 4) * 16 + v];
                a4 = __fmaf_rn(xv0, e.x, a4); a4 = __fmaf_rn(xv1, e.y, a4);
                a4 = __fmaf_rn(xv2, e.z, a4); a4 = __fmaf_rn(xv3, e.w, a4);
                e = esm[(mo + 5) * 16 + v];
                a5 = __fmaf_rn(xv0, e.x, a5); a5 = __fmaf_rn(xv1, e.y, a5);
                a5 = __fmaf_rn(xv2, e.z, a5); a5 = __fmaf_rn(xv3, e.w, a5);
                e = esm[(mo + 6) * 16 + v];
                a6 = __fmaf_rn(xv0, e.x, a6); a6 = __fmaf_rn(xv1, e.y, a6);
                a6 = __fmaf_rn(xv2, e.z, a6); a6 = __fmaf_rn(xv3, e.w, a6);
                e = esm[(mo + 7) * 16 + v];
                a7 = __fmaf_rn(xv0, e.x, a7); a7 = __fmaf_rn(xv1, e.y, a7);
                a7 = __fmaf_rn(xv2, e.z, a7); a7 = __fmaf_rn(xv3, e.w, a7);
            }
            const int gm = c * CHUNK + mo;
            float d2;
            d2 = __fadd_rn(__fsub_rn(x2, __fmul_rn(2.0f, a0)), e2s[mo + 0]);
            if (d2 < best) { best = d2; bestm = gm + 0; }
            d2 = __fadd_rn(__fsub_rn(x2, __fmul_rn(2.0f, a1)), e2s[mo + 1]);
            if (d2 < best) { best = d2; bestm = gm + 1; }
            d2 = __fadd_rn(__fsub_rn(x2, __fmul_rn(2.0f, a2)), e2s[mo + 2]);
            if (d2 < best) { best = d2; bestm = gm + 2; }
            d2 = __fadd_rn(__fsub_rn(x2, __fmul_rn(2.0f, a3)), e2s[mo + 3]);
            if (d2 < best) { best = d2; bestm = gm + 3; }
            d2 = __fadd_rn(__fsub_rn(x2, __fmul_rn(2.0f, a4)), e2s[mo + 4]);
            if (d2 < best) { best = d2; bestm = gm + 4; }
            d2 = __fadd_rn(__fsub_rn(x2, __fmul_rn(2.0f, a5)), e2s[mo + 5]);
            if (d2 < best) { best = d2; bestm = gm + 5; }
            d2 = __fadd_rn(__fsub_rn(x2, __fmul_rn(2.0f, a6)), e2s[mo + 6]);
            if (d2 < best) { best = d2; bestm = gm + 6; }
            d2 = __fadd_rn(__fsub_rn(x2, __fmul_rn(2.0f, a7)), e2s[mo + 7]);
            if (d2 < best) { best = d2; bestm = gm + 7; }
        }
    }

    // Emit quantized vector (straight-through: x + fl(q - x), matching ref rounding)
    // and accumulate commitment-loss partial sum.
    const float* eb    = emb + ((size_t)n * M_C + bestm) * D_C;  // hot in L2 (1 MB table)
    float*       obase = out + (size_t)(b * 512 + n * 64) * L_S + l;
    float lsum = 0.f;
#pragma unroll
    for (int d = 0; d < D_C; d++) {
        float q  = eb[d];
        float xv = xr[d];
        obase[(size_t)d * L_S] = __fadd_rn(xv, __fsub_rn(q, xv));
        float df = xv - q;
        lsum += df * df;
    }

    atomicAdd(&g_hist[n * M_C + bestm], 1);

    // Block-reduce loss partial, one double atomic per CTA
    __shared__ float red[TOK_PER_CTA / 32];
#pragma unroll
    for (int o = 16; o > 0; o >>= 1)
        lsum += __shfl_down_sync(0xffffffffu, lsum, o);
    if ((threadIdx.x & 31) == 0) red[threadIdx.x >> 5] = lsum;
    __syncthreads();
    if (threadIdx.x == 0) {
        float s = 0.f;
#pragma unroll
        for (int w = 0; w < TOK_PER_CTA / 32; w++) s += red[w];
        atomicAdd(&g_loss, (double)s);
    }
}

// Scalars: loss = 0.25 * mean((x-q)^2); perplexity = sum_n exp(-sum_m p*log(p+1e-10))
__global__ void vq_final(float* __restrict__ out, int loss_idx)
{
    __shared__ float pn[N_G];
    if (threadIdx.x < N_G) pn[threadIdx.x] = 0.f;
    __syncthreads();
    for (int i = threadIdx.x; i < N_G * M_C; i += blockDim.x) {
        float p = (float)g_hist[i] / (float)BL;
        atomicAdd(&pn[i / M_C], p * logf(p + 1e-10f));
    }
    __syncthreads();
    if (threadIdx.x == 0) {
        float perp = 0.f;
#pragma unroll
        for (int n = 0; n < N_G; n++) perp += expf(-pn[n]);
        double mean = g_loss / (double)((size_t)N_G * BL * D_C);
        out[loss_idx]     = (float)(0.25 * mean);
        out[loss_idx + 1] = perp;
    }
}

extern "C" void kernel_launch(void* const* d_in, const int* in_sizes, int n_in,
                              void* d_out, int out_size)
{
    const float* x   = (const float*)d_in[0];   // [32, 512, 1024] f32
    const float* emb = (const float*)d_in[1];   // [8, 512, 64]   f32
    float* out = (float*)d_out;                 // 16777216 + 2 scalars

    vq_zero<<<(N_G * M_C + 255) / 256, 256>>>();

    dim3 grid(BL / TOK_PER_CTA, N_G);
    vq_main<<<grid, TOK_PER_CTA>>>(x, emb, out);

    vq_final<<<1, 512>>>(out, out_size - 2);
}